// round 14
// baseline (speedup 1.0000x reference)
#include <cuda_runtime.h>
#include <cstdint>

// Spiking MLP: s2 = ((x @ W1^T >= 1) @ W2^T >= 1)
// Binary-activation LUT GEMM in s32:
//   weights -> rint(w * 2^28) (exact power-of-two scale), activations -> packed bits.
//   4 k's per nibble -> 16-entry smem LUT of subset sums -> 4B LDS per 4 MACs/col.
//   Crossbar roofline 128 MAC/cyc/SM = 2x the fp32 FFMA ceiling.

static const int M_BATCH = 4096;
static const int IN_DIM  = 3136;   // K of gemm1 (98 u32 words)
static const int FEAT    = 6272;   // N of gemm1 / K of gemm2 (196 u32 words)
static const int OUT_DIM = 500;
static const int OUT_PAD = 512;

#define QSCALE  268435456.0f       /* 2^28 (power of two: w*QSCALE exact) */
#define QTHRESH 268435456          /* threshold 1.0 * 2^28 */

// ---------------- device scratch (allocation-free rule) ----------------
__device__ int32_t  g_w1t[3136ull * 6272ull];   // W1^T quantized, [k][n]
__device__ int32_t  g_w2t[6272ull * 512ull];    // W2^T quantized, [k][n], n padded
__device__ uint32_t g_xn [4096ull * 98ull];     // x bits, bit (k%32) of word k/32
__device__ uint32_t g_s1n[4096ull * 196ull];    // hidden spike bits

// ---------------- conversion kernels ----------------
// x -> packed bits. One warp per row; ballot gives one u32 word per pass.
__global__ void cvt_x_bits_kernel(const float* __restrict__ x, uint32_t* __restrict__ xn)
{
    int m    = blockIdx.x * 8 + (threadIdx.x >> 5);
    int lane = threadIdx.x & 31;
    const float* row = x + (size_t)m * 3136;
    for (int c = 0; c < 4; c++) {
        int lim = min(32, 98 - c * 32);
        uint32_t w = 0;
        for (int i = 0; i < lim; i++) {
            float v = row[(c * 32 + i) * 32 + lane];
            uint32_t b = __ballot_sync(0xFFFFFFFFu, v >= 0.5f);
            if (lane == i) w = b;
        }
        if (lane < lim) xn[(size_t)m * 98 + c * 32 + lane] = w;
    }
}

// W1 [6272,3136] fp32 -> W1^T [3136][6272] s32 (writes coalesced)
__global__ void cvt_w1t_kernel(const float* __restrict__ w, int32_t* __restrict__ wt)
{
    int n = blockIdx.x * 256 + threadIdx.x;
    int k = blockIdx.y;
    if (n < 6272)
        wt[(size_t)k * 6272 + n] = __float2int_rn(w[(size_t)n * 3136 + k] * QSCALE);
}

// W2 [500,6272] fp32 -> W2^T [6272][512] s32, n zero-padded
__global__ void cvt_w2t_kernel(const float* __restrict__ w, int32_t* __restrict__ wt)
{
    int n = blockIdx.x * 256 + threadIdx.x;
    int k = blockIdx.y;
    float v = (n < 500) ? w[(size_t)n * 6272 + k] : 0.0f;
    wt[(size_t)k * 512 + n] = __float2int_rn(v * QSCALE);
}

// ---------------- LUT GEMM kernel ----------------
// C = threshold(Abits @ Wt_sum). Wt [K][NLD] s32 k-major; An [M][AnStride] bits.
// CTA tile: M = NWARPS*16, N = 256. Warp = 16 m x 256 n (lane owns 8 n).
// Per 16-k batch: build 4 nibble-LUTs (16 x 256 s32) in smem, then per (p,m):
// two int4 LDS per lane accumulate 4 k's into 8 n-accumulators.
template <int NWARPS>
__global__ void __launch_bounds__(NWARPS * 32, (NWARPS == 8) ? 1 : 2)
spike_lut_kernel(const int32_t* __restrict__ Wt,
                 const uint32_t* __restrict__ An,
                 int K, int NLD, int Nreal,
                 uint32_t* __restrict__ outBits, int outBitsStride,
                 float* __restrict__ outF,
                 int AnStride)
{
    extern __shared__ __align__(16) char smem[];
    int32_t  (*lut)[16][256] = (int32_t (*)[16][256])smem;          // 64 KB
    uint32_t* xs             = (uint32_t*)(smem + 65536);           // NWARPS*16 words

    const int tid  = threadIdx.x;
    const int lane = tid & 31;
    const int wid  = tid >> 5;
    const int n0   = blockIdx.x * 256;
    const int m0   = blockIdx.y * (NWARPS * 16);
    const int mw   = m0 + wid * 16;

    const int NB = K >> 4;                         // 16-k batches
    constexpr int NCOL = 256 / (NWARPS * 32);      // builder cols per thread

    int32_t acc[16][8];
#pragma unroll
    for (int m = 0; m < 16; m++)
#pragma unroll
        for (int j = 0; j < 8; j++) acc[m][j] = 0;

    int32_t wv[NCOL][4][4];
    uint32_t xr[16];

    // prefetch W for batch 0
#pragma unroll
    for (int c = 0; c < NCOL; c++) {
        const int col = n0 + c * (NWARPS * 32) + tid;
        const bool ok = (col < NLD);
#pragma unroll
        for (int p = 0; p < 4; p++)
#pragma unroll
            for (int j = 0; j < 4; j++)
                wv[c][p][j] = ok ? Wt[(size_t)(p * 4 + j) * NLD + col] : 0;
    }

    for (int b = 0; b < NB; b++) {
        // ---- build 4 LUTs from wv (subset-sum trick: 11 adds per nibble) ----
#pragma unroll
        for (int c = 0; c < NCOL; c++) {
            const int col = c * (NWARPS * 32) + tid;
#pragma unroll
            for (int p = 0; p < 4; p++) {
                int32_t e1  = wv[c][p][0];
                int32_t e2  = wv[c][p][1];
                int32_t e3  = e2 + e1;
                int32_t e4  = wv[c][p][2];
                int32_t e5  = e4 + e1;
                int32_t e6  = e4 + e2;
                int32_t e7  = e4 + e3;
                int32_t e8  = wv[c][p][3];
                lut[p][0][col]  = 0;
                lut[p][1][col]  = e1;
                lut[p][2][col]  = e2;
                lut[p][3][col]  = e3;
                lut[p][4][col]  = e4;
                lut[p][5][col]  = e5;
                lut[p][6][col]  = e6;
                lut[p][7][col]  = e7;
                lut[p][8][col]  = e8;
                lut[p][9][col]  = e8 + e1;
                lut[p][10][col] = e8 + e2;
                lut[p][11][col] = e8 + e3;
                lut[p][12][col] = e8 + e4;
                lut[p][13][col] = e8 + e5;
                lut[p][14][col] = e8 + e6;
                lut[p][15][col] = e8 + e7;
            }
        }
        // stage activation words for this batch pair
        if ((b & 1) == 0 && tid < NWARPS * 16)
            xs[tid] = An[(size_t)(m0 + tid) * AnStride + (b >> 1)];
        __syncthreads();

        // prefetch W for next batch (latency hidden by consume)
        if (b + 1 < NB) {
            const int kb = (b + 1) * 16;
#pragma unroll
            for (int c = 0; c < NCOL; c++) {
                const int col = n0 + c * (NWARPS * 32) + tid;
                const bool ok = (col < NLD);
#pragma unroll
                for (int p = 0; p < 4; p++)
#pragma unroll
                    for (int j = 0; j < 4; j++)
                        wv[c][p][j] = ok ? Wt[(size_t)(kb + p * 4 + j) * NLD + col] : 0;
            }
        }
        if ((b & 1) == 0) {
#pragma unroll
            for (int m = 0; m < 16; m++) xr[m] = xs[wid * 16 + m];
        }

        // ---- consume: 16 m x 4 nibbles, 2 int4 LDS per (p,m) per lane ----
        const uint32_t sh = (b & 1) * 16;
#pragma unroll
        for (int m = 0; m < 16; m++) {
            const uint32_t nv = xr[m] >> sh;
            const int32_t* p0 = &lut[0][(nv      ) & 15][lane * 8];
            const int32_t* p1 = &lut[1][(nv >>  4) & 15][lane * 8];
            const int32_t* p2 = &lut[2][(nv >>  8) & 15][lane * 8];
            const int32_t* p3 = &lut[3][(nv >> 12) & 15][lane * 8];
            int4 a0 = *(const int4*)(p0);
            int4 a1 = *(const int4*)(p0 + 4);
            int4 b0 = *(const int4*)(p1);
            int4 b1 = *(const int4*)(p1 + 4);
            int4 c0 = *(const int4*)(p2);
            int4 c1 = *(const int4*)(p2 + 4);
            int4 d0 = *(const int4*)(p3);
            int4 d1 = *(const int4*)(p3 + 4);
            acc[m][0] += a0.x + b0.x;  acc[m][0] += c0.x + d0.x;
            acc[m][1] += a0.y + b0.y;  acc[m][1] += c0.y + d0.y;
            acc[m][2] += a0.z + b0.z;  acc[m][2] += c0.z + d0.z;
            acc[m][3] += a0.w + b0.w;  acc[m][3] += c0.w + d0.w;
            acc[m][4] += a1.x + b1.x;  acc[m][4] += c1.x + d1.x;
            acc[m][5] += a1.y + b1.y;  acc[m][5] += c1.y + d1.y;
            acc[m][6] += a1.z + b1.z;  acc[m][6] += c1.z + d1.z;
            acc[m][7] += a1.w + b1.w;  acc[m][7] += c1.w + d1.w;
        }
        __syncthreads();
    }

    // ---- threshold epilogue ----
    if (outBits) {
        // pack spike bits: lane contributes 8 bits; word o gathers lanes 4o..4o+3
#pragma unroll
        for (int m = 0; m < 16; m++) {
            uint32_t byte = 0;
#pragma unroll
            for (int j = 0; j < 8; j++)
                byte |= (acc[m][j] >= QTHRESH ? 1u : 0u) << j;
            const int src = (lane & 7) * 4;
            uint32_t w = __shfl_sync(0xFFFFFFFFu, byte, src)
                       | (__shfl_sync(0xFFFFFFFFu, byte, src + 1) << 8)
                       | (__shfl_sync(0xFFFFFFFFu, byte, src + 2) << 16)
                       | (__shfl_sync(0xFFFFFFFFu, byte, src + 3) << 24);
            if (lane < 8) {
                const int col = (n0 >> 5) + lane;
                if (col < outBitsStride)
                    outBits[(size_t)(mw + m) * outBitsStride + col] = w;
            }
        }
    } else {
#pragma unroll
        for (int m = 0; m < 16; m++) {
            float* dst = outF + (size_t)(mw + m) * Nreal;
#pragma unroll
            for (int j = 0; j < 8; j++) {
                const int col = n0 + lane * 8 + j;
                if (col < Nreal)
                    dst[col] = (acc[m][j] >= QTHRESH) ? 1.0f : 0.0f;
            }
        }
    }
}

#define LUT_SMEM (65536 + 64 * 16)

// ---------------- host launch ----------------
extern "C" void kernel_launch(void* const* d_in, const int* in_sizes, int n_in,
                              void* d_out, int out_size)
{
    const float* x  = (const float*)d_in[0];   // [4096, 3136]
    const float* W1 = (const float*)d_in[1];   // [6272, 3136]
    const float* W2 = (const float*)d_in[2];   // [500, 6272]
    float* out = (float*)d_out;                // [4096, 500]

    int32_t  *w1t, *w2t;
    uint32_t *xn, *s1n;
    cudaGetSymbolAddress((void**)&w1t, g_w1t);
    cudaGetSymbolAddress((void**)&w2t, g_w2t);
    cudaGetSymbolAddress((void**)&xn,  g_xn);
    cudaGetSymbolAddress((void**)&s1n, g_s1n);

    cudaFuncSetAttribute(spike_lut_kernel<8>,
                         cudaFuncAttributeMaxDynamicSharedMemorySize, LUT_SMEM);
    cudaFuncSetAttribute(spike_lut_kernel<4>,
                         cudaFuncAttributeMaxDynamicSharedMemorySize, LUT_SMEM);

    // conversions (every call; deterministic)
    cvt_x_bits_kernel<<<M_BATCH / 8, 256>>>(x, xn);
    cvt_w1t_kernel<<<dim3((FEAT + 255) / 256, IN_DIM), 256>>>(W1, w1t);   // 25 blocks: full 6272 cols
    cvt_w2t_kernel<<<dim3(OUT_PAD / 256, FEAT), 256>>>(W2, w2t);

    // GEMM1: s1 bits = spike(x @ W1^T)   M=4096, N=6272, K=3136
    {
        dim3 grid((FEAT + 255) / 256, M_BATCH / 128);   // (25, 32)
        spike_lut_kernel<8><<<grid, 256, LUT_SMEM>>>(
            w1t, xn, IN_DIM, FEAT, FEAT, s1n, 196, nullptr, 98);
    }
    // GEMM2: out = spike(s1 @ W2^T)      M=4096, N=500 (pad 512), K=6272
    {
        dim3 grid(OUT_PAD / 256, M_BATCH / 64);         // (2, 64)
        spike_lut_kernel<4><<<grid, 128, LUT_SMEM>>>(
            w2t, s1n, FEAT, OUT_PAD, OUT_DIM, nullptr, 0, out, 196);
    }
}

// round 15
// speedup vs baseline: 1.9474x; 1.9474x over previous
#include <cuda_runtime.h>
#include <cstdint>

// Spiking MLP: s2 = ((x @ W1^T >= 1) @ W2^T >= 1)
// Binary-activation LUT GEMM in s32 (weights rint(w*2^28), activations bit-packed).
// 4 k's/nibble -> 16-entry smem LUT -> one int4 LDS per 16 MACs per lane.
// Round-15 fix: acc tile 16x4 (64 regs), N-tile 128, 32KB LUT, 2 CTAs/SM, no spills.

static const int M_BATCH = 4096;
static const int IN_DIM  = 3136;   // 98 u32 words
static const int FEAT    = 6272;   // 196 u32 words
static const int OUT_DIM = 500;
static const int OUT_PAD = 512;

#define QSCALE  268435456.0f       /* 2^28 (exact power-of-two scale) */
#define QTHRESH 268435456          /* 1.0 * 2^28 */

// ---------------- device scratch ----------------
__device__ int32_t  g_w1t[3136ull * 6272ull];   // W1^T quantized [k][n]
__device__ int32_t  g_w2t[6272ull * 512ull];    // W2^T quantized [k][n], padded
__device__ uint32_t g_xn [4096ull * 98ull];     // x bits
__device__ uint32_t g_s1n[4096ull * 196ull];    // hidden spike bits

// ---------------- conversion kernels ----------------
__global__ void cvt_x_bits_kernel(const float* __restrict__ x, uint32_t* __restrict__ xn)
{
    int m    = blockIdx.x * 8 + (threadIdx.x >> 5);
    int lane = threadIdx.x & 31;
    const float* row = x + (size_t)m * 3136;
    for (int c = 0; c < 4; c++) {
        int lim = min(32, 98 - c * 32);
        uint32_t w = 0;
        for (int i = 0; i < lim; i++) {
            float v = row[(c * 32 + i) * 32 + lane];
            uint32_t b = __ballot_sync(0xFFFFFFFFu, v >= 0.5f);
            if (lane == i) w = b;
        }
        if (lane < lim) xn[(size_t)m * 98 + c * 32 + lane] = w;
    }
}

__global__ void cvt_w1t_kernel(const float* __restrict__ w, int32_t* __restrict__ wt)
{
    int n = blockIdx.x * 256 + threadIdx.x;
    int k = blockIdx.y;
    if (n < 6272)
        wt[(size_t)k * 6272 + n] = __float2int_rn(w[(size_t)n * 3136 + k] * QSCALE);
}

__global__ void cvt_w2t_kernel(const float* __restrict__ w, int32_t* __restrict__ wt)
{
    int n = blockIdx.x * 256 + threadIdx.x;
    int k = blockIdx.y;
    float v = (n < 500) ? w[(size_t)n * 6272 + k] : 0.0f;
    wt[(size_t)k * 512 + n] = __float2int_rn(v * QSCALE);
}

// ---------------- LUT GEMM ----------------
// CTA: 256 threads = 8 warps. Tile M=128 (warp: 16 m), N=128 (lane: 4 cols).
// LUT [4][16][128] s32 = 32 KB; xs[128] activation words.
// N (=NLD) must be a multiple of 128; K a multiple of 32.
#define LUT_SMEM (32768 + 512)

__global__ void __launch_bounds__(256, 2)
spike_lut_kernel(const int32_t* __restrict__ Wt,
                 const uint32_t* __restrict__ An,
                 int K, int NLD, int Nreal,
                 uint32_t* __restrict__ outBits, int outBitsStride,
                 float* __restrict__ outF,
                 int AnStride)
{
    extern __shared__ __align__(16) char smem[];
    int32_t  (*lut)[16][128] = (int32_t (*)[16][128])smem;   // 32 KB
    uint32_t* xs             = (uint32_t*)(smem + 32768);    // 128 words

    const int tid  = threadIdx.x;
    const int lane = tid & 31;
    const int wid  = tid >> 5;
    const int n0   = blockIdx.x * 128;
    const int m0   = blockIdx.y * 128;

    const int NB = K >> 4;

    // build units: thread -> (p = tid>>7 and p+2, col = tid & 127)
    const int bcol = tid & 127;
    const int bp   = tid >> 7;          // 0 or 1; also builds bp+2

    int32_t acc[16][4];
#pragma unroll
    for (int m = 0; m < 16; m++)
#pragma unroll
        for (int j = 0; j < 4; j++) acc[m][j] = 0;

    int32_t wv[2][4];

    // prefetch W for batch 0
#pragma unroll
    for (int h = 0; h < 2; h++)
#pragma unroll
        for (int j = 0; j < 4; j++)
            wv[h][j] = Wt[(size_t)((bp + 2 * h) * 4 + j) * NLD + n0 + bcol];

    const uint32_t lutb = (uint32_t)(lane * 16);   // byte offset of this lane's 4 cols

    for (int b = 0; b < NB; b++) {
        // ---- build 2 nibble-LUT slices per thread (11 adds each) ----
#pragma unroll
        for (int h = 0; h < 2; h++) {
            const int p = bp + 2 * h;
            int32_t e1 = wv[h][0];
            int32_t e2 = wv[h][1];
            int32_t e3 = e2 + e1;
            int32_t e4 = wv[h][2];
            int32_t e5 = e4 + e1;
            int32_t e6 = e4 + e2;
            int32_t e7 = e4 + e3;
            int32_t e8 = wv[h][3];
            lut[p][0][bcol]  = 0;
            lut[p][1][bcol]  = e1;
            lut[p][2][bcol]  = e2;
            lut[p][3][bcol]  = e3;
            lut[p][4][bcol]  = e4;
            lut[p][5][bcol]  = e5;
            lut[p][6][bcol]  = e6;
            lut[p][7][bcol]  = e7;
            lut[p][8][bcol]  = e8;
            lut[p][9][bcol]  = e8 + e1;
            lut[p][10][bcol] = e8 + e2;
            lut[p][11][bcol] = e8 + e3;
            lut[p][12][bcol] = e8 + e4;
            lut[p][13][bcol] = e8 + e5;
            lut[p][14][bcol] = e8 + e6;
            lut[p][15][bcol] = e8 + e7;
        }
        if ((b & 1) == 0 && tid < 128)
            xs[tid] = An[(size_t)(m0 + tid) * AnStride + (b >> 1)];
        __syncthreads();

        // prefetch W for next batch (gmem latency hidden by consume)
        if (b + 1 < NB) {
            const int kb = (b + 1) << 4;
#pragma unroll
            for (int h = 0; h < 2; h++)
#pragma unroll
                for (int j = 0; j < 4; j++)
                    wv[h][j] = Wt[(size_t)(kb + (bp + 2 * h) * 4 + j) * NLD + n0 + bcol];
        }

        // ---- consume: 16 m rows, 4 int4 LDS each (conflict-free) ----
        const uint32_t sh = (b & 1) * 16;
        const char* lbase = smem + lutb;
#pragma unroll
        for (int m = 0; m < 16; m++) {
            const uint32_t nv = xs[wid * 16 + m] >> sh;   // LDS broadcast
            const int4 a = *(const int4*)(lbase +           (((nv      ) & 15) << 9));
            const int4 bq= *(const int4*)(lbase + 8192  +   (((nv >>  4) & 15) << 9));
            const int4 c = *(const int4*)(lbase + 16384 +   (((nv >>  8) & 15) << 9));
            const int4 d = *(const int4*)(lbase + 24576 +   (((nv >> 12) & 15) << 9));
            acc[m][0] += (a.x + bq.x) + (c.x + d.x);
            acc[m][1] += (a.y + bq.y) + (c.y + d.y);
            acc[m][2] += (a.z + bq.z) + (c.z + d.z);
            acc[m][3] += (a.w + bq.w) + (c.w + d.w);
        }
        __syncthreads();
    }

    // ---- threshold epilogue ----
    if (outBits) {
        // lane owns cols n0+lane*4..+3 -> nibble; butterfly-OR packs 8 lanes/word
#pragma unroll
        for (int m = 0; m < 16; m++) {
            uint32_t nib = 0;
#pragma unroll
            for (int j = 0; j < 4; j++)
                nib |= (acc[m][j] >= QTHRESH ? 1u : 0u) << j;
            uint32_t v = nib << ((lane & 7) * 4);
            v |= __shfl_xor_sync(0xFFFFFFFFu, v, 1);
            v |= __shfl_xor_sync(0xFFFFFFFFu, v, 2);
            v |= __shfl_xor_sync(0xFFFFFFFFu, v, 4);
            if ((lane & 7) == 0) {
                const int row = m0 + wid * 16 + m;
                outBits[(size_t)row * outBitsStride + (n0 >> 5) + (lane >> 3)] = v;
            }
        }
    } else {
#pragma unroll
        for (int m = 0; m < 16; m++) {
            const int row = m0 + wid * 16 + m;
            float* dst = outF + (size_t)row * Nreal;
#pragma unroll
            for (int j = 0; j < 4; j++) {
                const int col = n0 + lane * 4 + j;
                if (col < Nreal)
                    dst[col] = (acc[m][j] >= QTHRESH) ? 1.0f : 0.0f;
            }
        }
    }
}

// ---------------- host launch ----------------
extern "C" void kernel_launch(void* const* d_in, const int* in_sizes, int n_in,
                              void* d_out, int out_size)
{
    const float* x  = (const float*)d_in[0];   // [4096, 3136]
    const float* W1 = (const float*)d_in[1];   // [6272, 3136]
    const float* W2 = (const float*)d_in[2];   // [500, 6272]
    float* out = (float*)d_out;                // [4096, 500]

    int32_t  *w1t, *w2t;
    uint32_t *xn, *s1n;
    cudaGetSymbolAddress((void**)&w1t, g_w1t);
    cudaGetSymbolAddress((void**)&w2t, g_w2t);
    cudaGetSymbolAddress((void**)&xn,  g_xn);
    cudaGetSymbolAddress((void**)&s1n, g_s1n);

    cudaFuncSetAttribute(spike_lut_kernel,
                         cudaFuncAttributeMaxDynamicSharedMemorySize, LUT_SMEM);

    // conversions (deterministic, every call)
    cvt_x_bits_kernel<<<M_BATCH / 8, 256>>>(x, xn);
    cvt_w1t_kernel<<<dim3((FEAT + 255) / 256, IN_DIM), 256>>>(W1, w1t);
    cvt_w2t_kernel<<<dim3(OUT_PAD / 256, FEAT), 256>>>(W2, w2t);

    // GEMM1: s1 bits = spike(x @ W1^T)   M=4096, N=6272, K=3136
    {
        dim3 grid(FEAT / 128, M_BATCH / 128);   // (49, 32)
        spike_lut_kernel<<<grid, 256, LUT_SMEM>>>(
            w1t, xn, IN_DIM, FEAT, FEAT, s1n, 196, nullptr, 98);
    }
    // GEMM2: out = spike(s1 @ W2^T)      M=4096, N=512 pad, K=6272
    {
        dim3 grid(OUT_PAD / 128, M_BATCH / 128);  // (4, 32)
        spike_lut_kernel<<<grid, 256, LUT_SMEM>>>(
            w2t, s1n, FEAT, OUT_PAD, OUT_DIM, nullptr, 0, out, 196);
    }
}